// round 9
// baseline (speedup 1.0000x reference)
#include <cuda_runtime.h>
#include <cstdint>

#define OUTD 11008
#define IND  4096
#define GCNT 704512
#define CDIM 172
#define NB   8
#define ICHUNK 512
#define NIT  4                      /* 128 groups per iter (4 per lane, int4) */

typedef unsigned long long ull;

__device__ float T_dev[CDIM * NB];                     // zero-point column sums

// packed f32x2 helpers (sm_100+)
__device__ __forceinline__ void fma2(ull& acc, ull a, ull b) {
    asm("fma.rn.f32x2 %0, %1, %2, %0;" : "+l"(acc) : "l"(a), "l"(b));
}
__device__ __forceinline__ ull add2(ull a, ull b) {
    ull r; asm("add.rn.f32x2 %0, %1, %2;" : "=l"(r) : "l"(a), "l"(b)); return r;
}
__device__ __forceinline__ ull pack2(float v) {
    ull r; asm("mov.b64 %0, {%1, %1};" : "=l"(r) : "f"(v)); return r;
}
__device__ __forceinline__ ull pack2f(float a, float b) {
    ull r; asm("mov.b64 %0, {%1, %2};" : "=l"(r) : "f"(a), "f"(b)); return r;
}

// ---------------------------------------------------------------------------
// Kernel A: T[c,b] = sum_i z[c,i]*s[c,i]*x[b,i]  (one block per c)
// ---------------------------------------------------------------------------
__global__ __launch_bounds__(256) void tsum_kernel(
    const float* __restrict__ scale, const float* __restrict__ zero,
    const float* __restrict__ x) {
    __shared__ ull red[256 * 4];
    const int c = blockIdx.x, tid = threadIdx.x;

    ull tl[4] = {0ull, 0ull, 0ull, 0ull};
    for (int k = tid; k < IND; k += 256) {
        const float zs = zero[c * IND + k] * scale[c * IND + k];
        #pragma unroll
        for (int p = 0; p < 4; ++p) {
            ull xv = pack2f(x[(2 * p) * IND + k] * zs,
                            x[(2 * p + 1) * IND + k] * zs);
            tl[p] = add2(tl[p], xv);
        }
    }
    #pragma unroll
    for (int p = 0; p < 4; ++p) red[tid * 4 + p] = tl[p];
    __syncthreads();
    for (int s = 128; s >= 1; s >>= 1) {
        if (tid < s) {
            #pragma unroll
            for (int p = 0; p < 4; ++p)
                red[tid * 4 + p] = add2(red[tid * 4 + p], red[(tid + s) * 4 + p]);
        }
        __syncthreads();
    }
    if (tid < NB) T_dev[c * NB + tid] = reinterpret_cast<float*>(red)[tid];
}

// ---------------------------------------------------------------------------
// Kernel B: out[b,o] = bias[o] - T[o%172, b]
// ---------------------------------------------------------------------------
__global__ void init_out_kernel(const float* __restrict__ bias,
                                float* __restrict__ out) {
    int idx = blockIdx.x * blockDim.x + threadIdx.x;
    if (idx < NB * OUTD) {
        int b = idx / OUTD, o = idx % OUTD;
        out[idx] = bias[o] - T_dev[(o % CDIM) * NB + b];
    }
}

// ---------------------------------------------------------------------------
// Kernel C: main loop. Block = (c, i-chunk of 512). Warp w owns Wq rows
// 4w..4w+3 (8 output rows via hi/lo nibbles). x is staged PRE-SCALED by s
// (y = s*x), so the inner MAC is just nibble * y: no s/z in the hot loop.
// ---------------------------------------------------------------------------
__global__ __launch_bounds__(256, 2) void hqq_gemv_kernel(
    const int*   __restrict__ Wq,     // [32, 704512] int32 (one byte per elem)
    const float* __restrict__ scale,  // [704512]
    const float* __restrict__ x,      // [8, 4096]
    float*       __restrict__ out)    // [8, 11008]
{
    // y pair-planes: plane p = (j&3)*4 + bp holds {y[2bp][j], y[2bp+1][j]}
    // at index j>>2 -> lane-consecutive, conflict-free LDS.64.
    __shared__ ull xsm[16 * 128];                      // 16 KB

    const int tid = threadIdx.x;
    const int h   = blockIdx.x & 7;                    // i-chunk
    const int c   = blockIdx.x >> 3;                   // 0..171
    const int ib  = h * ICHUNK;

    for (int k = tid; k < 4 * ICHUNK; k += 256) {      // 2048 entries
        int bp = k >> 9, j = k & (ICHUNK - 1);
        float sv = scale[c * IND + ib + j];
        float lo = x[(2 * bp)     * IND + ib + j] * sv;
        float hi = x[(2 * bp + 1) * IND + ib + j] * sv;
        xsm[((j & 3) * 4 + bp) * 128 + (j >> 2)] = pack2f(lo, hi);
    }
    __syncthreads();

    const int w    = tid >> 5;                         // warp 0..7
    const int l    = tid & 31;
    const int wrow = w << 2;                           // Wq rows wrow..wrow+3
    const int g0   = c * IND + ib;                     // stripe base (16B-aligned)

    const int4* qp0 = (const int4*)(Wq + (long)(wrow + 0) * GCNT + g0) + l;
    const int4* qp1 = (const int4*)(Wq + (long)(wrow + 1) * GCNT + g0) + l;
    const int4* qp2 = (const int4*)(Wq + (long)(wrow + 2) * GCNT + g0) + l;
    const int4* qp3 = (const int4*)(Wq + (long)(wrow + 3) * GCNT + g0) + l;

    ull acc[32];                                       // [rp*8 + 0..3]=hi, 4..7=lo
    #pragma unroll
    for (int i = 0; i < 32; ++i) acc[i] = 0ull;

    // prefetch iter 0 (4x LDG.128)
    int4 qa = __ldg(qp0), qb = __ldg(qp1), qc = __ldg(qp2), qd = __ldg(qp3);

    #pragma unroll
    for (int it = 0; it < NIT; ++it) {
        // prefetch next stripe (last iter: in-bounds re-read of stripe 0)
        const int off = (it + 1 < NIT) ? (it + 1) * 32 : 0;
        int4 qan = __ldg(qp0 + off), qbn = __ldg(qp1 + off);
        int4 qcn = __ldg(qp2 + off), qdn = __ldg(qp3 + off);

        const int qra[4] = {qa.x, qa.y, qa.z, qa.w};
        const int qrb[4] = {qb.x, qb.y, qb.z, qb.w};
        const int qrc[4] = {qc.x, qc.y, qc.z, qc.w};
        const int qrd[4] = {qd.x, qd.y, qd.z, qd.w};

        #pragma unroll
        for (int jo = 0; jo < 4; ++jo) {               // substep = one group
            const ull* xr = xsm + (jo * 4) * 128 + it * 32 + l;
            const ull x01 = xr[0], x23 = xr[128], x45 = xr[256], x67 = xr[384];

            // Exact nibbles: lo via 2^23 magic, hi via 2^19 magic (bits 4-7
            // land at mantissa[4:7] so value = 2^19 + nh exactly).
#define DOROW(QV, RP)                                                          \
            {                                                                  \
                float fl = __int_as_float(((QV) & 0x0F) | 0x4B000000) - 8388608.f; \
                float fh = __int_as_float(((QV) & 0xF0) | 0x49000000) - 524288.f;  \
                ull wh2 = pack2(fh), wl2 = pack2(fl);                          \
                fma2(acc[(RP)*8 + 0], x01, wh2); fma2(acc[(RP)*8 + 1], x23, wh2); \
                fma2(acc[(RP)*8 + 2], x45, wh2); fma2(acc[(RP)*8 + 3], x67, wh2); \
                fma2(acc[(RP)*8 + 4], x01, wl2); fma2(acc[(RP)*8 + 5], x23, wl2); \
                fma2(acc[(RP)*8 + 6], x45, wl2); fma2(acc[(RP)*8 + 7], x67, wl2); \
            }
            DOROW(qra[jo], 0) DOROW(qrb[jo], 1) DOROW(qrc[jo], 2) DOROW(qrd[jo], 3)
#undef DOROW
        }

        qa = qan; qb = qbn; qc = qcn; qd = qdn;
    }

    // Butterfly halving exchange: 32 f32x2 per lane -> lane l holds item l
    // summed over all 32 lanes. item k: rp=k>>3, half=(k>>2)&1, pair=k&3.
    #pragma unroll
    for (int d = 16; d >= 1; d >>= 1) {
        const bool up = (l & d) != 0;
        #pragma unroll
        for (int k = 0; k < d; ++k) {
            ull send = up ? acc[k] : acc[k + d];
            ull got  = __shfl_xor_sync(0xffffffffu, send, d);
            ull keep = up ? acc[k + d] : acc[k];
            acc[k] = add2(keep, got);
        }
    }

    float fx, fy;
    asm("mov.b64 {%0, %1}, %2;" : "=f"(fx), "=f"(fy) : "l"(acc[0]));
    const int rp = l >> 3, half = (l >> 2) & 1, pair = l & 3;
    const int o  = (wrow + rp + half * 32) * CDIM + c;
    atomicAdd(out + (2 * pair)     * OUTD + o, fx);
    atomicAdd(out + (2 * pair + 1) * OUTD + o, fy);
}

// ---------------------------------------------------------------------------
extern "C" void kernel_launch(void* const* d_in, const int* in_sizes, int n_in,
                              void* d_out, int out_size) {
    const int*   Wq    = (const int*)  d_in[0];
    const float* scale = (const float*)d_in[1];
    const float* zero  = (const float*)d_in[2];
    const float* x     = (const float*)d_in[3];
    const float* bias  = (const float*)d_in[4];
    float* out = (float*)d_out;

    tsum_kernel<<<CDIM, 256>>>(scale, zero, x);
    init_out_kernel<<<(NB * OUTD + 255) / 256, 256>>>(bias, out);
    hqq_gemv_kernel<<<CDIM * (IND / ICHUNK), 256>>>(Wq, scale, x, out);
}